// round 6
// baseline (speedup 1.0000x reference)
#include <cuda_runtime.h>
#include <math.h>
#include <stdint.h>

#define TT    64
#define BATCH 4096
#define HID   256
#define BB    8          // batches per CTA
#define NP    4          // b-pairs per CTA
#define SROW  516        // floats per pair-row (256 float2 + 2 pad), 16B-aligned
#define NCTA  512
#define NTHR  128

// Raw per-step outputs: [cta][t][b_local][c], c = {spk0, spk1, mem0, mem1}
__device__ float g_vals[NCTA * TT * BB * 4];
// Splatted weights: row h = 512 floats, [j] -> {w, w}
__device__ float g_WhS [HID * 2 * HID];
__device__ float g_Wh2S[HID * 2 * HID];

// One packed f32x2 FMA: two independent fp32 RN FMAs (lanes = batch pair)
#define FMA2(acc, s, w) \
    asm("fma.rn.f32x2 %0, %1, %2, %0;" : "+l"(acc) : "l"(s), "l"(w))

__device__ __forceinline__ float clamp01(float v) {
    return fminf(fmaxf(v, 0.0f), 1.0f);
}

__global__ void prep(const float* __restrict__ Wh, const float* __restrict__ Wh2)
{
    int i = blockIdx.x * blockDim.x + threadIdx.x;   // 0..65535
    float a = Wh[i], b = Wh2[i];
    int h = i >> 8, j = i & 255;
    int o = h * 512 + j * 2;
    g_WhS [o] = a; g_WhS [o + 1] = a;
    g_Wh2S[o] = b; g_Wh2S[o + 1] = b;
}

// One hidden layer for this thread's two h-units (h0, h1 = h0+128), 8 batches.
// Each f32x2 lane executes the exact serial ascending fmaf chain from 0.
__device__ __forceinline__ void layer_f2(
    const float* __restrict__ Wsp0,  // splatted row of h0 (512 floats)
    const float* __restrict__ Wsp1,  // splatted row of h1
    const float* __restrict__ Sin,   // packed spikes [NP][SROW]
    float*       __restrict__ Sout,
    float bias0, float beta0, float thr0,
    float bias1, float beta1, float thr1,
    float* __restrict__ m0, float* __restrict__ m1,
    int h0, int h1)
{
    unsigned long long a0[NP], a1[NP];
    #pragma unroll
    for (int p = 0; p < NP; p++) { a0[p] = 0ull; a1[p] = 0ull; }

    #pragma unroll 2
    for (int j0 = 0; j0 < HID; j0 += 2) {
        ulonglong2 w0 = *(const ulonglong2*)(Wsp0 + j0 * 2);
        ulonglong2 w1 = *(const ulonglong2*)(Wsp1 + j0 * 2);
        #pragma unroll
        for (int p = 0; p < NP; p++) {
            ulonglong2 s = *(const ulonglong2*)(Sin + p * SROW + j0 * 2);
            FMA2(a0[p], s.x, w0.x);
            FMA2(a0[p], s.y, w0.y);
            FMA2(a1[p], s.x, w1.x);
            FMA2(a1[p], s.y, w1.y);
        }
    }

    #pragma unroll
    for (int p = 0; p < NP; p++) {
        float2 v0 = *(float2*)&a0[p];   // .x -> b=2p, .y -> b=2p+1 (for h0)
        float2 v1 = *(float2*)&a1[p];
        {
            float cur = __fadd_rn(v0.x, bias0);
            float rst = (__fsub_rn(m0[2*p], thr0) > 0.f) ? thr0 : 0.f;
            m0[2*p] = __fsub_rn(fmaf(beta0, m0[2*p], cur), rst);
            Sout[p * SROW + 2*h0 + 0] = (__fsub_rn(m0[2*p], thr0) > 0.f) ? 1.f : 0.f;
        }
        {
            float cur = __fadd_rn(v0.y, bias0);
            float rst = (__fsub_rn(m0[2*p+1], thr0) > 0.f) ? thr0 : 0.f;
            m0[2*p+1] = __fsub_rn(fmaf(beta0, m0[2*p+1], cur), rst);
            Sout[p * SROW + 2*h0 + 1] = (__fsub_rn(m0[2*p+1], thr0) > 0.f) ? 1.f : 0.f;
        }
        {
            float cur = __fadd_rn(v1.x, bias1);
            float rst = (__fsub_rn(m1[2*p], thr1) > 0.f) ? thr1 : 0.f;
            m1[2*p] = __fsub_rn(fmaf(beta1, m1[2*p], cur), rst);
            Sout[p * SROW + 2*h1 + 0] = (__fsub_rn(m1[2*p], thr1) > 0.f) ? 1.f : 0.f;
        }
        {
            float cur = __fadd_rn(v1.y, bias1);
            float rst = (__fsub_rn(m1[2*p+1], thr1) > 0.f) ? thr1 : 0.f;
            m1[2*p+1] = __fsub_rn(fmaf(beta1, m1[2*p+1], cur), rst);
            Sout[p * SROW + 2*h1 + 1] = (__fsub_rn(m1[2*p+1], thr1) > 0.f) ? 1.f : 0.f;
        }
    }
}

__global__ __launch_bounds__(NTHR, 4) void snn_main(
    const float* __restrict__ x,
    const float* __restrict__ W_in,  const float* __restrict__ b_in,
    const float* __restrict__ beta_in, const float* __restrict__ thr_in,
    const float* __restrict__ b_h,   const float* __restrict__ beta_h,
    const float* __restrict__ thr_h,
    const float* __restrict__ b_h2,  const float* __restrict__ beta_h2,
    const float* __restrict__ thr_h2,
    const float* __restrict__ W_out, const float* __restrict__ b_out,
    const float* __restrict__ beta_out)
{
    __shared__ __align__(16) float SA[NP * SROW];   // s1 / s4 (disjoint lifetimes)
    __shared__ __align__(16) float SB[NP * SROW];   // s2
    __shared__ float xs[BB * 3];
    __shared__ float embs[TT];

    const int tid = threadIdx.x;
    const int h0  = tid;
    const int h1  = tid + 128;
    const int cta = blockIdx.x;
    const int b0  = cta * BB;

    if (tid < TT) {
        double z  = (tid - 32.0) / 6.4;
        double e  = exp(-0.5 * (z * z));
        double e0 = exp(-12.5);
        embs[tid] = (float)((e - e0) / (1.0 - e0));
    }

    // Per-h parameters (two h-units per thread)
    const float wi00 = W_in[h0*3+0], wi01 = W_in[h0*3+1], wi02 = W_in[h0*3+2];
    const float wi10 = W_in[h1*3+0], wi11 = W_in[h1*3+1], wi12 = W_in[h1*3+2];
    const float bin0 = b_in[h0], bt10 = clamp01(beta_in[h0]), th10 = thr_in[h0];
    const float bin1 = b_in[h1], bt11 = clamp01(beta_in[h1]), th11 = thr_in[h1];
    const float bh0  = b_h[h0],  bt20 = clamp01(beta_h[h0]),  th20 = thr_h[h0];
    const float bh1  = b_h[h1],  bt21 = clamp01(beta_h[h1]),  th21 = thr_h[h1];
    const float bq0  = b_h2[h0], bt30 = clamp01(beta_h2[h0]), th30 = thr_h2[h0];
    const float bq1  = b_h2[h1], bt31 = clamp01(beta_h2[h1]), th31 = thr_h2[h1];

    float m1[2*BB], m2[2*BB], m4[2*BB];
    #pragma unroll
    for (int i = 0; i < 2*BB; i++) { m1[i] = 0.f; m2[i] = 0.f; m4[i] = 0.f; }

    // Output LI layer state: lanes tid<16, (b = tid>>1, o = tid&1)
    float m3 = 0.f, btO = 0.f, bO = 0.f;
    const int ob = tid >> 1, oo = tid & 1;
    if (tid < 16) { btO = clamp01(beta_out[oo]); bO = b_out[oo]; }

    const float* Wh0  = g_WhS  + h0 * 512;
    const float* Wh1  = g_WhS  + h1 * 512;
    const float* Wq0  = g_Wh2S + h0 * 512;
    const float* Wq1  = g_Wh2S + h1 * 512;

    __syncthreads();

    for (int t = 0; t < TT; t++) {
        if (tid < BB * 3)
            xs[tid] = __fmul_rn(x[(t * BATCH + b0) * 3 + tid], embs[t]);
        __syncthreads();

        // Layer 1 (3 -> H): same chain as the passing kernel
        #pragma unroll
        for (int b = 0; b < BB; b++) {
            float x0 = xs[b*3], x1v = xs[b*3+1], x2v = xs[b*3+2];
            float d = fmaf(x0, wi00, 0.0f);
            d = fmaf(x1v, wi01, d);
            d = fmaf(x2v, wi02, d);
            float cur = __fadd_rn(d, bin0);
            float rst = (__fsub_rn(m1[b], th10) > 0.f) ? th10 : 0.f;
            m1[b] = __fsub_rn(fmaf(bt10, m1[b], cur), rst);
            SA[(b>>1)*SROW + 2*h0 + (b&1)] = (__fsub_rn(m1[b], th10) > 0.f) ? 1.f : 0.f;

            float e = fmaf(x0, wi10, 0.0f);
            e = fmaf(x1v, wi11, e);
            e = fmaf(x2v, wi12, e);
            float cur1 = __fadd_rn(e, bin1);
            float rst1 = (__fsub_rn(m1[BB+b], th11) > 0.f) ? th11 : 0.f;
            m1[BB+b] = __fsub_rn(fmaf(bt11, m1[BB+b], cur1), rst1);
            SA[(b>>1)*SROW + 2*h1 + (b&1)] = (__fsub_rn(m1[BB+b], th11) > 0.f) ? 1.f : 0.f;
        }
        __syncthreads();

        // Layer 2: s2 = LIF(W_h @ s1)
        layer_f2(Wh0, Wh1, SA, SB, bh0, bt20, th20, bh1, bt21, th21,
                 m2, m2 + BB, h0, h1);
        __syncthreads();

        // Layer 3: s4 = LIF(W_h2 @ s2)
        layer_f2(Wq0, Wq1, SB, SA, bq0, bt30, th30, bq1, bt31, th31,
                 m4, m4 + BB, h0, h1);
        __syncthreads();

        // Output LI (lanes 0..15): exact ascending-h serial chain
        if (tid < 16) {
            const float* wrow = W_out + oo * HID;
            const float* srow = SA + (ob >> 1) * SROW + (ob & 1);
            float dot = 0.0f;
            #pragma unroll 8
            for (int hh = 0; hh < HID; hh++)
                dot = fmaf(srow[2*hh], wrow[hh], dot);
            m3 = __fadd_rn(fmaf(btO, m3, dot), bO);
            float spk = (__fsub_rn(m3, 1.0f) > 0.0f) ? 1.0f : 0.0f;

            float* dst = g_vals + ((cta * TT + t) * BB + ob) * 4;
            dst[oo]     = spk;
            dst[2 + oo] = m3;
        }
        __syncthreads();
    }
}

// out[r][o] = sum_k reshaped[r][k] * W_pred[o][k] + b_pred[o], ascending k.
// r = t*64 + g; k -> b = g*64 + (k>>2), c = k&3; cta = b>>3 = g*8 + (k>>5).
__global__ void snn_finalize(const float* __restrict__ W_pred,
                             const float* __restrict__ b_pred,
                             float* __restrict__ out)
{
    int idx = blockIdx.x * blockDim.x + threadIdx.x;
    if (idx >= BATCH * 2) return;
    int r = idx >> 1, o = idx & 1;
    int t = r >> 6, g = r & 63;

    const float* wp = W_pred + o * (TT * 4);
    float acc = 0.0f;
    #pragma unroll 4
    for (int k = 0; k < TT * 4; k++) {
        float v = g_vals[((g * 8 + (k >> 5)) * TT + t) * 32 + (k & 31)];
        acc = fmaf(v, wp[k], acc);
    }
    out[idx] = __fadd_rn(acc, b_pred[o]);
}

extern "C" void kernel_launch(void* const* d_in, const int* in_sizes, int n_in,
                              void* d_out, int out_size)
{
    const float* x        = (const float*)d_in[0];
    const float* W_in     = (const float*)d_in[1];
    const float* b_in     = (const float*)d_in[2];
    const float* beta_in  = (const float*)d_in[3];
    const float* thr_in   = (const float*)d_in[4];
    const float* W_h      = (const float*)d_in[5];
    const float* b_h      = (const float*)d_in[6];
    const float* beta_h   = (const float*)d_in[7];
    const float* thr_h    = (const float*)d_in[8];
    const float* W_h2     = (const float*)d_in[9];
    const float* b_h2     = (const float*)d_in[10];
    const float* beta_h2  = (const float*)d_in[11];
    const float* thr_h2   = (const float*)d_in[12];
    const float* W_out    = (const float*)d_in[13];
    const float* b_out    = (const float*)d_in[14];
    const float* beta_out = (const float*)d_in[15];
    const float* W_pred   = (const float*)d_in[16];
    const float* b_pred   = (const float*)d_in[17];
    float* out = (float*)d_out;

    prep<<<256, 256>>>(W_h, W_h2);
    snn_main<<<NCTA, NTHR>>>(x, W_in, b_in, beta_in, thr_in,
                             b_h, beta_h, thr_h,
                             b_h2, beta_h2, thr_h2,
                             W_out, b_out, beta_out);
    snn_finalize<<<32, 256>>>(W_pred, b_pred, out);
}

// round 8
// speedup vs baseline: 2.9005x; 2.9005x over previous
#include <cuda_runtime.h>
#include <math.h>
#include <stdint.h>

#define TT    64
#define BATCH 4096
#define HID   256
#define BB    16         // batches per CTA
#define GB    8          // batches per thread-group (2 groups)
#define SROW  516        // floats per duplicated spike row (512 + 4 pad)
#define NCTA  256
#define NTHR  256

// Raw per-step outputs: [cta][t][b_local][c], c = {spk0, spk1, mem0, mem1}
__device__ float g_vals[NCTA * TT * BB * 4];
// Pair-packed weights: group g=j/2, pair p=h/2:
//   Wpk[(g*128+p)*4 + {0,1,2,3}] = {W[2p][2g], W[2p+1][2g], W[2p][2g+1], W[2p+1][2g+1]}
__device__ __align__(16) float g_WhP [HID * HID];
__device__ __align__(16) float g_Wh2P[HID * HID];

// One packed f32x2 FMA: two independent fp32 RN FMAs (lanes = h-pair)
#define FMA2(acc, s, w) \
    asm("fma.rn.f32x2 %0, %1, %2, %0;" : "+l"(acc) : "l"(s), "l"(w))

__device__ __forceinline__ float clamp01(float v) {
    return fminf(fmaxf(v, 0.0f), 1.0f);
}

__global__ void prep(const float* __restrict__ Wh, const float* __restrict__ Wh2)
{
    int i = blockIdx.x * blockDim.x + threadIdx.x;   // 0..65535
    int h = i >> 8, j = i & 255;
    int p = h >> 1, e = h & 1, g = j >> 1, f = j & 1;
    int dst = (g * 128 + p) * 4 + f * 2 + e;
    g_WhP [dst] = Wh[i];
    g_Wh2P[dst] = Wh2[i];
}

// Hidden layer for this thread: h-pair (h0=2u, h1=2u+1), 8 batches (one group).
// FFMA2 lane0 = h0 chain, lane1 = h1 chain; j ascending 0..255, start 0,
// bias added after -> bit-identical to the round-5 passing numerics.
__device__ __forceinline__ void layer_f2(
    const float* __restrict__ Wpk,    // packed weight matrix (64K floats)
    const float* __restrict__ Sin,    // duplicated spikes [BB][SROW]
    float*       __restrict__ Sout,
    float bias0, float beta0, float thr0,
    float bias1, float beta1, float thr1,
    float* __restrict__ m0,           // [8] membranes for h0
    float* __restrict__ m1,           // [8] membranes for h1
    int u, int bg)                    // pair index, batch-group base (0 or 8)
{
    unsigned long long acc[GB];
    #pragma unroll
    for (int k = 0; k < GB; k++) acc[k] = 0ull;

    const float* Sbase = Sin + bg * SROW;

    #pragma unroll 4
    for (int g2 = 0; g2 < 128; g2++) {
        ulonglong2 w = *(const ulonglong2*)(Wpk + (g2 * 128 + u) * 4);
        #pragma unroll
        for (int k = 0; k < GB; k++) {
            ulonglong2 s = *(const ulonglong2*)(Sbase + k * SROW + g2 * 4);
            FMA2(acc[k], s.x, w.x);   // j = 2*g2
            FMA2(acc[k], s.y, w.y);   // j = 2*g2 + 1
        }
    }

    #pragma unroll
    for (int k = 0; k < GB; k++) {
        float2 v = *(float2*)&acc[k];   // .x -> h0, .y -> h1
        float s0, s1;
        {
            float cur = __fadd_rn(v.x, bias0);
            float rst = (__fsub_rn(m0[k], thr0) > 0.f) ? thr0 : 0.f;
            m0[k] = __fsub_rn(fmaf(beta0, m0[k], cur), rst);
            s0 = (__fsub_rn(m0[k], thr0) > 0.f) ? 1.f : 0.f;
        }
        {
            float cur = __fadd_rn(v.y, bias1);
            float rst = (__fsub_rn(m1[k], thr1) > 0.f) ? thr1 : 0.f;
            m1[k] = __fsub_rn(fmaf(beta1, m1[k], cur), rst);
            s1 = (__fsub_rn(m1[k], thr1) > 0.f) ? 1.f : 0.f;
        }
        *(float4*)(Sout + (bg + k) * SROW + 4 * u) = make_float4(s0, s0, s1, s1);
    }
}

extern __shared__ float smdyn[];

__global__ __launch_bounds__(NTHR, 2) void snn_main(
    const float* __restrict__ x,
    const float* __restrict__ W_in,  const float* __restrict__ b_in,
    const float* __restrict__ beta_in, const float* __restrict__ thr_in,
    const float* __restrict__ b_h,   const float* __restrict__ beta_h,
    const float* __restrict__ thr_h,
    const float* __restrict__ b_h2,  const float* __restrict__ beta_h2,
    const float* __restrict__ thr_h2,
    const float* __restrict__ W_out, const float* __restrict__ b_out,
    const float* __restrict__ beta_out)
{
    float* SA   = smdyn;                 // s1 / s4 (disjoint lifetimes), [16][SROW]
    float* SB   = SA + BB * SROW;        // s2
    float* xs   = SB + BB * SROW;        // [48]
    float* embs = xs + 64;               // [64]

    const int tid = threadIdx.x;
    const int u   = tid & 127;           // h-pair index
    const int grp = tid >> 7;            // batch group 0/1
    const int bg  = grp * GB;            // local batch base
    const int h0  = 2 * u, h1 = 2 * u + 1;
    const int cta = blockIdx.x;
    const int b0  = cta * BB;

    if (tid < TT) {
        double z  = (tid - 32.0) / 6.4;
        double e  = exp(-0.5 * (z * z));
        double e0 = exp(-12.5);
        embs[tid] = (float)((e - e0) / (1.0 - e0));
    }

    // Per-h parameters for this thread's h-pair
    const float wi00 = W_in[h0*3+0], wi01 = W_in[h0*3+1], wi02 = W_in[h0*3+2];
    const float wi10 = W_in[h1*3+0], wi11 = W_in[h1*3+1], wi12 = W_in[h1*3+2];
    const float bin0 = b_in[h0], bt10 = clamp01(beta_in[h0]), th10 = thr_in[h0];
    const float bin1 = b_in[h1], bt11 = clamp01(beta_in[h1]), th11 = thr_in[h1];
    const float bh0  = b_h[h0],  bt20 = clamp01(beta_h[h0]),  th20 = thr_h[h0];
    const float bh1  = b_h[h1],  bt21 = clamp01(beta_h[h1]),  th21 = thr_h[h1];
    const float bq0  = b_h2[h0], bt30 = clamp01(beta_h2[h0]), th30 = thr_h2[h0];
    const float bq1  = b_h2[h1], bt31 = clamp01(beta_h2[h1]), th31 = thr_h2[h1];

    // Membranes: [h-of-pair][local batch 0..7]
    float m1a[GB], m1b[GB], m2a[GB], m2b[GB], m4a[GB], m4b[GB];
    #pragma unroll
    for (int k = 0; k < GB; k++) {
        m1a[k] = 0.f; m1b[k] = 0.f; m2a[k] = 0.f;
        m2b[k] = 0.f; m4a[k] = 0.f; m4b[k] = 0.f;
    }

    // Output LI state: lanes tid<32, (b = tid>>1 in 0..15, o = tid&1)
    float m3 = 0.f, btO = 0.f, bO = 0.f;
    const int ob = tid >> 1, oo = tid & 1;
    if (tid < 32) { btO = clamp01(beta_out[oo]); bO = b_out[oo]; }

    __syncthreads();

    for (int t = 0; t < TT; t++) {
        if (tid < BB * 3)
            xs[tid] = __fmul_rn(x[(t * BATCH + b0) * 3 + tid], embs[t]);
        __syncthreads();

        // Layer 1 (3 -> H), exact round-5 chain, duplicated spike store
        #pragma unroll
        for (int k = 0; k < GB; k++) {
            int b = bg + k;
            float x0 = xs[b*3], x1v = xs[b*3+1], x2v = xs[b*3+2];
            float d = fmaf(x0, wi00, 0.0f);
            d = fmaf(x1v, wi01, d);
            d = fmaf(x2v, wi02, d);
            float cur = __fadd_rn(d, bin0);
            float rst = (__fsub_rn(m1a[k], th10) > 0.f) ? th10 : 0.f;
            m1a[k] = __fsub_rn(fmaf(bt10, m1a[k], cur), rst);
            float s0 = (__fsub_rn(m1a[k], th10) > 0.f) ? 1.f : 0.f;

            float e = fmaf(x0, wi10, 0.0f);
            e = fmaf(x1v, wi11, e);
            e = fmaf(x2v, wi12, e);
            float cur1 = __fadd_rn(e, bin1);
            float rst1 = (__fsub_rn(m1b[k], th11) > 0.f) ? th11 : 0.f;
            m1b[k] = __fsub_rn(fmaf(bt11, m1b[k], cur1), rst1);
            float s1 = (__fsub_rn(m1b[k], th11) > 0.f) ? 1.f : 0.f;

            *(float4*)(SA + b * SROW + 4 * u) = make_float4(s0, s0, s1, s1);
        }
        __syncthreads();

        // Layer 2: s2 = LIF(W_h @ s1)
        layer_f2(g_WhP, SA, SB, bh0, bt20, th20, bh1, bt21, th21,
                 m2a, m2b, u, bg);
        __syncthreads();

        // Layer 3: s4 = LIF(W_h2 @ s2)
        layer_f2(g_Wh2P, SB, SA, bq0, bt30, th30, bq1, bt31, th31,
                 m4a, m4b, u, bg);
        __syncthreads();

        // Output LI (lanes 0..31 -> all 16 batches x 2 outputs):
        // exact ascending-h serial chain over duplicated spikes
        if (tid < 32) {
            const float* wrow = W_out + oo * HID;
            const float* srow = SA + ob * SROW;
            float dot = 0.0f;
            #pragma unroll 8
            for (int hh = 0; hh < HID; hh++)
                dot = fmaf(srow[2*hh], wrow[hh], dot);
            m3 = __fadd_rn(fmaf(btO, m3, dot), bO);
            float spk = (__fsub_rn(m3, 1.0f) > 0.0f) ? 1.0f : 0.0f;

            float* dst = g_vals + ((cta * TT + t) * BB + ob) * 4;
            dst[oo]     = spk;
            dst[2 + oo] = m3;
        }
        __syncthreads();
    }
}

// out[r][o] = sum_k reshaped[r][k] * W_pred[o][k] + b_pred[o], ascending k.
// r = t*64 + g; k -> b = g*64 + (k>>2); cta = b>>4 = g*4 + (k>>6);
// within-cta offset (t*BB + (b&15))*4 + (k&3) = t*64 + (k&63).
__global__ void snn_finalize(const float* __restrict__ W_pred,
                             const float* __restrict__ b_pred,
                             float* __restrict__ out)
{
    int idx = blockIdx.x * blockDim.x + threadIdx.x;
    if (idx >= BATCH * 2) return;
    int r = idx >> 1, o = idx & 1;
    int t = r >> 6, g = r & 63;

    const float* wp = W_pred + o * (TT * 4);
    float acc = 0.0f;
    #pragma unroll 4
    for (int k = 0; k < TT * 4; k++) {
        float v = g_vals[(g * 4 + (k >> 6)) * (TT * 64) + t * 64 + (k & 63)];
        acc = fmaf(v, wp[k], acc);
    }
    out[idx] = __fadd_rn(acc, b_pred[o]);
}

extern "C" void kernel_launch(void* const* d_in, const int* in_sizes, int n_in,
                              void* d_out, int out_size)
{
    const float* x        = (const float*)d_in[0];
    const float* W_in     = (const float*)d_in[1];
    const float* b_in     = (const float*)d_in[2];
    const float* beta_in  = (const float*)d_in[3];
    const float* thr_in   = (const float*)d_in[4];
    const float* W_h      = (const float*)d_in[5];
    const float* b_h      = (const float*)d_in[6];
    const float* beta_h   = (const float*)d_in[7];
    const float* thr_h    = (const float*)d_in[8];
    const float* W_h2     = (const float*)d_in[9];
    const float* b_h2     = (const float*)d_in[10];
    const float* beta_h2  = (const float*)d_in[11];
    const float* thr_h2   = (const float*)d_in[12];
    const float* W_out    = (const float*)d_in[13];
    const float* b_out    = (const float*)d_in[14];
    const float* beta_out = (const float*)d_in[15];
    const float* W_pred   = (const float*)d_in[16];
    const float* b_pred   = (const float*)d_in[17];
    float* out = (float*)d_out;

    const int smem_bytes = (2 * BB * SROW + 64 + TT) * sizeof(float);
    static int attr_set = 0;
    if (!attr_set) {
        cudaFuncSetAttribute(snn_main,
                             cudaFuncAttributeMaxDynamicSharedMemorySize,
                             smem_bytes);
        attr_set = 1;
    }

    prep<<<256, 256>>>(W_h, W_h2);
    snn_main<<<NCTA, NTHR, smem_bytes>>>(x, W_in, b_in, beta_in, thr_in,
                                         b_h, beta_h, thr_h,
                                         b_h2, beta_h2, thr_h2,
                                         W_out, b_out, beta_out);
    snn_finalize<<<32, 256>>>(W_pred, b_pred, out);
}

// round 9
// speedup vs baseline: 2.9266x; 1.0090x over previous
#include <cuda_runtime.h>
#include <math.h>
#include <stdint.h>

#define TT    64
#define BATCH 4096
#define HID   256
#define BB    32         // batches per CTA
#define GB    8          // batches per thread-group (4 groups)
#define SROW  516        // floats per duplicated spike row (512 + 4 pad)
#define NCTA  128
#define NTHR  256

// Raw per-step outputs: [cta][t][b_local][c], c = {spk0, spk1, mem0, mem1}
__device__ float g_vals[NCTA * TT * BB * 4];
// Pair-packed weights: group g=j/2, pair p=h/2:
//   Wpk[(g*128+p)*4 + {0,1,2,3}] = {W[2p][2g], W[2p+1][2g], W[2p][2g+1], W[2p+1][2g+1]}
__device__ __align__(16) float g_WhP [HID * HID];
__device__ __align__(16) float g_Wh2P[HID * HID];

// One packed f32x2 FMA: two independent fp32 RN FMAs (lanes = h-pair)
#define FMA2(acc, s, w) \
    asm("fma.rn.f32x2 %0, %1, %2, %0;" : "+l"(acc) : "l"(s), "l"(w))

__device__ __forceinline__ float clamp01(float v) {
    return fminf(fmaxf(v, 0.0f), 1.0f);
}

__global__ void prep(const float* __restrict__ Wh, const float* __restrict__ Wh2)
{
    int i = blockIdx.x * blockDim.x + threadIdx.x;   // 0..65535
    int h = i >> 8, j = i & 255;
    int p = h >> 1, e = h & 1, g = j >> 1, f = j & 1;
    int dst = (g * 128 + p) * 4 + f * 2 + e;
    g_WhP [dst] = Wh[i];
    g_Wh2P[dst] = Wh2[i];
}

// Hidden layer for this thread: h-quad (4u..4u+3 = pairs 2u, 2u+1), 8 batches.
// Each FFMA2 lane executes the exact serial ascending-j fmaf chain from 0,
// bias added after -> bit-identical to the round-5 passing numerics.
__device__ __forceinline__ void layer_q(
    const float* __restrict__ Wpk,    // packed weight matrix (64K floats)
    const float* __restrict__ Sin,    // duplicated spikes, group base
    float*       __restrict__ Sout,   // group base
    const float* __restrict__ bias,   // [4] per-h params (register arrays)
    const float* __restrict__ beta,
    const float* __restrict__ thr,
    float (* __restrict__ m)[GB],     // [4][GB] membranes
    int u)
{
    unsigned long long accA[GB], accB[GB];
    #pragma unroll
    for (int k = 0; k < GB; k++) { accA[k] = 0ull; accB[k] = 0ull; }

    #pragma unroll 2
    for (int g2 = 0; g2 < 128; g2++) {
        const float* wp = Wpk + g2 * 512 + 8 * u;   // (g2*128 + 2u)*4
        ulonglong2 wA = *(const ulonglong2*)(wp);       // pair 2u   (h 4u,4u+1)
        ulonglong2 wB = *(const ulonglong2*)(wp + 4);   // pair 2u+1 (h 4u+2,4u+3)
        #pragma unroll
        for (int k = 0; k < GB; k++) {
            ulonglong2 s = *(const ulonglong2*)(Sin + k * SROW + g2 * 4);
            FMA2(accA[k], s.x, wA.x);   // j = 2*g2
            FMA2(accA[k], s.y, wA.y);   // j = 2*g2 + 1
            FMA2(accB[k], s.x, wB.x);
            FMA2(accB[k], s.y, wB.y);
        }
    }

    #pragma unroll
    for (int k = 0; k < GB; k++) {
        float2 vA = *(float2*)&accA[k];   // .x -> h=4u,   .y -> h=4u+1
        float2 vB = *(float2*)&accB[k];   // .x -> h=4u+2, .y -> h=4u+3
        float dots[4] = { vA.x, vA.y, vB.x, vB.y };
        float s[4];
        #pragma unroll
        for (int e = 0; e < 4; e++) {
            float cur = __fadd_rn(dots[e], bias[e]);
            float rst = (__fsub_rn(m[e][k], thr[e]) > 0.f) ? thr[e] : 0.f;
            m[e][k] = __fsub_rn(fmaf(beta[e], m[e][k], cur), rst);
            s[e] = (__fsub_rn(m[e][k], thr[e]) > 0.f) ? 1.f : 0.f;
        }
        float* dst = Sout + k * SROW + 8 * u;
        *(float4*)(dst)     = make_float4(s[0], s[0], s[1], s[1]);
        *(float4*)(dst + 4) = make_float4(s[2], s[2], s[3], s[3]);
    }
}

extern __shared__ float smdyn[];

__global__ __launch_bounds__(NTHR, 1) void snn_main(
    const float* __restrict__ x,
    const float* __restrict__ W_in,  const float* __restrict__ b_in,
    const float* __restrict__ beta_in, const float* __restrict__ thr_in,
    const float* __restrict__ b_h,   const float* __restrict__ beta_h,
    const float* __restrict__ thr_h,
    const float* __restrict__ b_h2,  const float* __restrict__ beta_h2,
    const float* __restrict__ thr_h2,
    const float* __restrict__ W_out, const float* __restrict__ b_out,
    const float* __restrict__ beta_out)
{
    float* SA   = smdyn;                 // s1 / s4 (disjoint lifetimes), [32][SROW]
    float* SB   = SA + BB * SROW;        // s2
    float* xs   = SB + BB * SROW;        // [96]
    float* embs = xs + 96;               // [64]

    const int tid = threadIdx.x;
    const int u   = tid & 63;            // h-quad index
    const int grp = tid >> 6;            // batch group 0..3
    const int bg  = grp * GB;            // local batch base
    const int cta = blockIdx.x;
    const int b0  = cta * BB;

    if (tid < TT) {
        double z  = (tid - 32.0) / 6.4;
        double e  = exp(-0.5 * (z * z));
        double e0 = exp(-12.5);
        embs[tid] = (float)((e - e0) / (1.0 - e0));
    }

    // Per-h parameters for this thread's h-quad
    float wi[4][3];
    float bin[4], bt1[4], th1[4];
    float bh [4], bt2[4], th2[4];
    float bq [4], bt3[4], th3[4];
    #pragma unroll
    for (int e = 0; e < 4; e++) {
        int h = 4 * u + e;
        wi[e][0] = W_in[h*3+0]; wi[e][1] = W_in[h*3+1]; wi[e][2] = W_in[h*3+2];
        bin[e] = b_in[h];  bt1[e] = clamp01(beta_in[h]);  th1[e] = thr_in[h];
        bh [e] = b_h[h];   bt2[e] = clamp01(beta_h[h]);   th2[e] = thr_h[h];
        bq [e] = b_h2[h];  bt3[e] = clamp01(beta_h2[h]);  th3[e] = thr_h2[h];
    }

    // Membranes: [h-of-quad][local batch 0..7]
    float m1[4][GB], m2[4][GB], m4[4][GB];
    #pragma unroll
    for (int e = 0; e < 4; e++)
        #pragma unroll
        for (int k = 0; k < GB; k++) { m1[e][k] = 0.f; m2[e][k] = 0.f; m4[e][k] = 0.f; }

    // Output LI state: lanes tid<64, (b = tid>>1 in 0..31, o = tid&1)
    float m3 = 0.f, btO = 0.f, bO = 0.f;
    const int ob = tid >> 1, oo = tid & 1;
    if (tid < 64) { btO = clamp01(beta_out[oo]); bO = b_out[oo]; }

    float* SinG  = SA + bg * SROW;   // group-local views
    float* SoutG = SB + bg * SROW;

    __syncthreads();

    for (int t = 0; t < TT; t++) {
        if (tid < BB * 3)
            xs[tid] = __fmul_rn(x[(t * BATCH + b0) * 3 + tid], embs[t]);
        __syncthreads();

        // Layer 1 (3 -> H), exact round-5 chain, duplicated spike store
        #pragma unroll
        for (int k = 0; k < GB; k++) {
            int b = bg + k;
            float x0 = xs[b*3], x1v = xs[b*3+1], x2v = xs[b*3+2];
            float s[4];
            #pragma unroll
            for (int e = 0; e < 4; e++) {
                float d = fmaf(x0, wi[e][0], 0.0f);
                d = fmaf(x1v, wi[e][1], d);
                d = fmaf(x2v, wi[e][2], d);
                float cur = __fadd_rn(d, bin[e]);
                float rst = (__fsub_rn(m1[e][k], th1[e]) > 0.f) ? th1[e] : 0.f;
                m1[e][k] = __fsub_rn(fmaf(bt1[e], m1[e][k], cur), rst);
                s[e] = (__fsub_rn(m1[e][k], th1[e]) > 0.f) ? 1.f : 0.f;
            }
            float* dst = SA + b * SROW + 8 * u;
            *(float4*)(dst)     = make_float4(s[0], s[0], s[1], s[1]);
            *(float4*)(dst + 4) = make_float4(s[2], s[2], s[3], s[3]);
        }
        __syncthreads();

        // Layer 2: s2 = LIF(W_h @ s1)
        layer_q(g_WhP, SinG, SoutG, bh, bt2, th2, m2, u);
        __syncthreads();

        // Layer 3: s4 = LIF(W_h2 @ s2)
        layer_q(g_Wh2P, SoutG, SinG, bq, bt3, th3, m4, u);
        __syncthreads();

        // Output LI (lanes 0..63 -> 32 batches x 2 outputs):
        // exact ascending-h serial chain over duplicated spikes
        if (tid < 64) {
            const float* wrow = W_out + oo * HID;
            const float* srow = SA + ob * SROW;
            float dot = 0.0f;
            #pragma unroll 8
            for (int hh = 0; hh < HID; hh++)
                dot = fmaf(srow[2*hh], wrow[hh], dot);
            m3 = __fadd_rn(fmaf(btO, m3, dot), bO);
            float spk = (__fsub_rn(m3, 1.0f) > 0.0f) ? 1.0f : 0.0f;

            float* dst = g_vals + ((cta * TT + t) * BB + ob) * 4;
            dst[oo]     = spk;
            dst[2 + oo] = m3;
        }
        __syncthreads();
    }
}

// out[r][o] = sum_k reshaped[r][k] * W_pred[o][k] + b_pred[o], ascending k.
// r = t*64 + g; k -> b = g*64 + (k>>2); cta = b>>5 = 2g + (k>>7);
// within-cta offset (t*BB + (b&31))*4 + (k&3) = t*128 + (k&127).
__global__ void snn_finalize(const float* __restrict__ W_pred,
                             const float* __restrict__ b_pred,
                             float* __restrict__ out)
{
    int idx = blockIdx.x * blockDim.x + threadIdx.x;
    if (idx >= BATCH * 2) return;
    int r = idx >> 1, o = idx & 1;
    int t = r >> 6, g = r & 63;

    const float* wp = W_pred + o * (TT * 4);
    float acc = 0.0f;
    #pragma unroll 4
    for (int k = 0; k < TT * 4; k++) {
        float v = g_vals[((2 * g + (k >> 7)) * TT + t) * 128 + (k & 127)];
        acc = fmaf(v, wp[k], acc);
    }
    out[idx] = __fadd_rn(acc, b_pred[o]);
}

extern "C" void kernel_launch(void* const* d_in, const int* in_sizes, int n_in,
                              void* d_out, int out_size)
{
    const float* x        = (const float*)d_in[0];
    const float* W_in     = (const float*)d_in[1];
    const float* b_in     = (const float*)d_in[2];
    const float* beta_in  = (const float*)d_in[3];
    const float* thr_in   = (const float*)d_in[4];
    const float* W_h      = (const float*)d_in[5];
    const float* b_h      = (const float*)d_in[6];
    const float* beta_h   = (const float*)d_in[7];
    const float* thr_h    = (const float*)d_in[8];
    const float* W_h2     = (const float*)d_in[9];
    const float* b_h2     = (const float*)d_in[10];
    const float* beta_h2  = (const float*)d_in[11];
    const float* thr_h2   = (const float*)d_in[12];
    const float* W_out    = (const float*)d_in[13];
    const float* b_out    = (const float*)d_in[14];
    const float* beta_out = (const float*)d_in[15];
    const float* W_pred   = (const float*)d_in[16];
    const float* b_pred   = (const float*)d_in[17];
    float* out = (float*)d_out;

    const int smem_bytes = (2 * BB * SROW + 96 + TT) * sizeof(float);
    static int attr_set = 0;
    if (!attr_set) {
        cudaFuncSetAttribute(snn_main,
                             cudaFuncAttributeMaxDynamicSharedMemorySize,
                             smem_bytes);
        attr_set = 1;
    }

    prep<<<256, 256>>>(W_h, W_h2);
    snn_main<<<NCTA, NTHR, smem_bytes>>>(x, W_in, b_in, beta_in, thr_in,
                                         b_h, beta_h, thr_h,
                                         b_h2, beta_h2, thr_h2,
                                         W_out, b_out, beta_out);
    snn_finalize<<<32, 256>>>(W_pred, b_pred, out);
}